// round 1
// baseline (speedup 1.0000x reference)
#include <cuda_runtime.h>
#include <math.h>

#define BATCH 16384
#define NINP  768
#define NHID  360
#define NBLK  6
#define BSZ   60

// ---------------- scratch ----------------
__device__ float g_kv[BATCH*496];      // [b][0:256]=Kproj (head-major 4x64), [256:496]=Vproj (head-major 4x60)
__device__ float g_q[BATCH*1536];      // [b][k*256 + h*64 + c]
__device__ float g_alpha[BATCH*24];    // [b][k*4+h] = sigma(s1)
__device__ float g_mask[BATCH*6];      // 0/1
__device__ float g_gates[BATCH*1440];  // [b][k*240 + g*60 + r]
__device__ float g_hxn[BATCH*360];     // LSTM hx_new (pre comm-attn)
__device__ float g_qkvc[BATCH*2304];   // [b][k*384 + {0:q,128:k,256:v}]
__device__ float g_raw[BATCH*768];     // [b][i*128 + h*32 + c]

__device__ __forceinline__ float sigf(float x){ return 1.f/(1.f+expf(-x)); }

#define FMA16(acc, pa, pb) do { \
  float4 a_ = *(const float4*)(pa); \
  float4 b_ = *(const float4*)(pb); \
  acc[ 0] += a_.x*b_.x; acc[ 1] += a_.x*b_.y; acc[ 2] += a_.x*b_.z; acc[ 3] += a_.x*b_.w; \
  acc[ 4] += a_.y*b_.x; acc[ 5] += a_.y*b_.y; acc[ 6] += a_.y*b_.z; acc[ 7] += a_.y*b_.w; \
  acc[ 8] += a_.z*b_.x; acc[ 9] += a_.z*b_.y; acc[10] += a_.z*b_.z; acc[11] += a_.z*b_.w; \
  acc[12] += a_.w*b_.x; acc[13] += a_.w*b_.y; acc[14] += a_.w*b_.z; acc[15] += a_.w*b_.w; \
} while(0)

// ---------------- K1: KV projection  [B,768] @ [768,496] ----------------
// Wk1 = Wk_inp + 768*256 (module 1), Wv1 = Wv_inp + 768*240 (module 1)
__global__ void k1_kvproj(const float* __restrict__ inp,
                          const float* __restrict__ Wk1,
                          const float* __restrict__ Wv1)
{
    __shared__ __align__(16) float As[16*68];
    __shared__ __align__(16) float Bs[16*68];
    int tid = threadIdx.x;
    int tx = tid & 15, ty = tid >> 4;
    int m0 = blockIdx.y * 64;
    int n0 = blockIdx.x * 64;
    float acc[16];
#pragma unroll
    for (int i = 0; i < 16; i++) acc[i] = 0.f;

    for (int k0 = 0; k0 < 768; k0 += 16) {
        for (int e = tid; e < 64*16; e += 256) {
            int m = e >> 4, d = e & 15;
            As[d*68 + m] = inp[(size_t)(m0+m)*768 + k0 + d];
        }
        for (int e = tid; e < 16*64; e += 256) {
            int d = e >> 6, n = e & 63;
            int ng = n0 + n;
            float v = 0.f;
            if (ng < 256)       v = Wk1[(size_t)(k0+d)*256 + ng];
            else if (ng < 496)  v = Wv1[(size_t)(k0+d)*240 + (ng-256)];
            Bs[d*68 + n] = v;
        }
        __syncthreads();
#pragma unroll
        for (int kk = 0; kk < 16; kk++)
            FMA16(acc, &As[kk*68 + ty*4], &Bs[kk*68 + tx*4]);
        __syncthreads();
    }
#pragma unroll
    for (int i = 0; i < 4; i++) {
        int m = m0 + ty*4 + i;
#pragma unroll
        for (int j = 0; j < 4; j++) {
            int n = n0 + tx*4 + j;
            if (n < 496) g_kv[(size_t)m*496 + n] = acc[i*4+j];
        }
    }
}

// ---------------- K2: Q projection per block  [B,60] @ Wq[k] [60,256] ----------------
__global__ void k2_qproj(const float* __restrict__ hx,
                         const float* __restrict__ Wq)
{
    __shared__ __align__(16) float Xs[60*68];
    __shared__ __align__(16) float Ws[60*68];
    int tid = threadIdx.x;
    int tx = tid & 15, ty = tid >> 4;
    int m0 = blockIdx.x * 64;
    int k  = blockIdx.y;
    int n0 = blockIdx.z * 64;

    for (int e = tid; e < 64*60; e += 256) {
        int m = e / 60, d = e % 60;
        Xs[d*68 + m] = hx[(size_t)(m0+m)*360 + k*60 + d];
    }
    for (int e = tid; e < 60*64; e += 256) {
        int d = e >> 6, n = e & 63;
        Ws[d*68 + n] = Wq[(size_t)k*15360 + d*256 + n0 + n];
    }
    __syncthreads();
    float acc[16];
#pragma unroll
    for (int i = 0; i < 16; i++) acc[i] = 0.f;
#pragma unroll 10
    for (int kk = 0; kk < 60; kk++)
        FMA16(acc, &Xs[kk*68 + ty*4], &Ws[kk*68 + tx*4]);
#pragma unroll
    for (int i = 0; i < 4; i++) {
        int m = m0 + ty*4 + i;
#pragma unroll
        for (int j = 0; j < 4; j++) {
            int n = n0 + tx*4 + j;
            g_q[(size_t)m*1536 + k*256 + n] = acc[i*4+j];
        }
    }
}

// ---------------- K3: scores, alpha, top-2 null mask ----------------
__global__ void k3_attmask()
{
    int w = threadIdx.x >> 5, lane = threadIdx.x & 31;
    int b = blockIdx.x * 8 + w;
    __shared__ float s_al[8][25];
    __shared__ float s_nul[8][8];

    if (lane < 24) {
        const float* qp = g_q  + (size_t)b*1536 + lane*64;
        const float* kp = g_kv + (size_t)b*496  + (lane & 3)*64;
        float s = 0.f;
#pragma unroll 8
        for (int c = 0; c < 64; c++) s += qp[c]*kp[c];
        s *= 0.125f;                       // 1/sqrt(64)
        float a = sigf(s);                 // softmax([0,s])[1]
        g_alpha[(size_t)b*24 + lane] = a;
        s_al[w][lane] = a;
    }
    __syncwarp();
    if (lane < 6) {
        float n = 1.f - 0.25f*(s_al[w][lane*4] + s_al[w][lane*4+1] +
                               s_al[w][lane*4+2] + s_al[w][lane*4+3]);
        s_nul[w][lane] = n;
    }
    __syncwarp();
    if (lane == 0) {
        int i1 = 0; float m1 = s_nul[w][0];
        for (int k = 1; k < 6; k++) if (s_nul[w][k] > m1) { m1 = s_nul[w][k]; i1 = k; }
        int i2 = -1; float m2 = -1e30f;
        for (int k = 0; k < 6; k++) if (k != i1 && s_nul[w][k] > m2) { m2 = s_nul[w][k]; i2 = k; }
        for (int k = 0; k < 6; k++)
            g_mask[(size_t)b*6 + k] = (k == i1 || k == i2) ? 0.f : 1.f;
    }
}

// ---------------- K4: LSTM gates, block-diag GEMM  [B,300] @ [300,60] per (gate,block) ----------------
__global__ void k4_gates(const float* __restrict__ hx,
                         const float* __restrict__ W_ih,
                         const float* __restrict__ W_hh,
                         const float* __restrict__ b_ih,
                         const float* __restrict__ b_hh)
{
    __shared__ __align__(16) float As[20*68];
    __shared__ __align__(16) float Bs[20*68];
    __shared__ float s_alpha[64*4];
    int tid = threadIdx.x;              // 240
    int tx = tid % 15, ty = tid / 15;
    int g  = blockIdx.x;                // gate 0..3
    int m0 = blockIdx.y * 64;
    int k  = blockIdx.z;                // block 0..5

    for (int e = tid; e < 256; e += 240)
        s_alpha[e] = g_alpha[(size_t)(m0 + (e >> 2))*24 + k*4 + (e & 3)];
    __syncthreads();

    float acc[16];
#pragma unroll
    for (int i = 0; i < 16; i++) acc[i] = 0.f;

    for (int d0 = 0; d0 < 300; d0 += 20) {
        for (int e = tid; e < 64*20; e += 240) {
            int m = e / 20, dd = e % 20;
            int d = d0 + dd;
            float v;
            if (d < 240) v = s_alpha[m*4 + d/60] * g_kv[(size_t)(m0+m)*496 + 256 + d];
            else         v = hx[(size_t)(m0+m)*360 + k*60 + (d-240)];
            As[dd*68 + m] = v;
        }
        for (int e = tid; e < 20*60; e += 240) {
            int c = e / 20, dd = e % 20;
            int d = d0 + dd;
            int rowW = g*360 + k*60 + c;
            float v;
            if (d < 240) v = W_ih[(size_t)rowW*1440 + k*240 + d];
            else         v = W_hh[(size_t)rowW*360  + k*60  + (d-240)];
            Bs[dd*68 + c] = v;
        }
        __syncthreads();
#pragma unroll
        for (int kk = 0; kk < 20; kk++)
            FMA16(acc, &As[kk*68 + ty*4], &Bs[kk*68 + tx*4]);
        __syncthreads();
    }
#pragma unroll
    for (int i = 0; i < 4; i++) {
        int m = m0 + ty*4 + i;
#pragma unroll
        for (int j = 0; j < 4; j++) {
            int c = tx*4 + j;
            int rowW = g*360 + k*60 + c;
            g_gates[(size_t)m*1440 + k*240 + g*60 + c] = acc[i*4+j] + b_ih[rowW] + b_hh[rowW];
        }
    }
}

// ---------------- K5: LSTM pointwise + final cx_out ----------------
__global__ void k5_lstm(const float* __restrict__ cx, float* __restrict__ out_cx)
{
    int idx = blockIdx.x*256 + threadIdx.x;       // < BATCH*360
    int b = idx / 360, j = idx % 360;
    int k = j / 60,   r = j % 60;
    const float* gp = g_gates + (size_t)b*1440 + k*240 + r;
    float gi = gp[0], gf = gp[60], gg = gp[120], go = gp[180];
    float c_old = cx[idx];
    float cn = sigf(gf)*c_old + sigf(gi)*tanhf(gg);
    float hn = sigf(go)*tanhf(cn);
    g_hxn[idx] = hn;
    float m = g_mask[(size_t)b*6 + k];
    out_cx[idx] = m*cn + (1.f - m)*c_old;
}

// ---------------- K6: comm QKV per block  [B,60] @ [60,384] ----------------
__global__ void k6_commqkv(const float* __restrict__ Wq_c,
                           const float* __restrict__ Wk_c,
                           const float* __restrict__ Wv_c)
{
    __shared__ __align__(16) float Xs[60*68];
    __shared__ __align__(16) float Ws[60*68];
    int tid = threadIdx.x;
    int tx = tid & 15, ty = tid >> 4;
    int m0 = blockIdx.x * 64;
    int k  = blockIdx.y;
    int ng0 = blockIdx.z * 64;  // 0..320

    for (int e = tid; e < 64*60; e += 256) {
        int m = e / 60, d = e % 60;
        Xs[d*68 + m] = g_hxn[(size_t)(m0+m)*360 + k*60 + d];
    }
    const float* Wsel = (ng0 < 128) ? Wq_c : (ng0 < 256) ? Wk_c : Wv_c;
    int nc0 = ng0 & 127;
    for (int e = tid; e < 60*64; e += 256) {
        int d = e >> 6, n = e & 63;
        Ws[d*68 + n] = Wsel[(size_t)k*7680 + d*128 + nc0 + n];
    }
    __syncthreads();
    float acc[16];
#pragma unroll
    for (int i = 0; i < 16; i++) acc[i] = 0.f;
#pragma unroll 10
    for (int kk = 0; kk < 60; kk++)
        FMA16(acc, &Xs[kk*68 + ty*4], &Ws[kk*68 + tx*4]);
#pragma unroll
    for (int i = 0; i < 4; i++) {
        int m = m0 + ty*4 + i;
#pragma unroll
        for (int j = 0; j < 4; j++) {
            int n = ng0 + tx*4 + j;
            g_qkvc[(size_t)m*2304 + k*384 + n] = acc[i*4+j];
        }
    }
}

// ---------------- K7: communication attention (6 tokens, 4 heads x 32) ----------------
__global__ void k7_commattn()
{
    __shared__ float sq[4][2304];
    __shared__ float ss[4][144];
    int w = threadIdx.x >> 5, lane = threadIdx.x & 31;
    int b = blockIdx.x * 4 + w;
    const float* src = g_qkvc + (size_t)b*2304;
    for (int t = lane; t < 2304; t += 32) sq[w][t] = src[t];
    __syncwarp();

    const float inv = 0.17677669529663687f;  // 1/sqrt(32)
    for (int p = lane; p < 144; p += 32) {
        int h = p / 36, rem = p % 36, i = rem / 6, j = rem % 6;
        const float* qv = &sq[w][i*384 + h*32];
        const float* kv = &sq[w][j*384 + 128 + h*32];
        float s = 0.f;
#pragma unroll
        for (int c = 0; c < 32; c++) s += qv[c]*kv[c];
        ss[w][p] = s * inv;
    }
    __syncwarp();
    if (lane < 24) {
        float* row = &ss[w][lane*6];     // lane = h*6+i
        float mx = row[0];
#pragma unroll
        for (int j = 1; j < 6; j++) mx = fmaxf(mx, row[j]);
        float ev[6]; float sum = 0.f;
#pragma unroll
        for (int j = 0; j < 6; j++) { ev[j] = expf(row[j]-mx); sum += ev[j]; }
        float is = 1.f/sum;
#pragma unroll
        for (int j = 0; j < 6; j++) row[j] = ev[j]*is;
    }
    __syncwarp();
    for (int o = lane; o < 768; o += 32) {
        int i = o >> 7, rem = o & 127, h = rem >> 5, c = rem & 31;
        const float* att = &ss[w][h*36 + i*6];
        float acc = 0.f;
#pragma unroll
        for (int j = 0; j < 6; j++) acc += att[j]*sq[w][j*384 + 256 + h*32 + c];
        g_raw[(size_t)b*768 + o] = acc;
    }
}

// ---------------- K8: fc/gate GEMM (interleaved cols) + final hx_out ----------------
__global__ void k8_fcgate_out(const float* __restrict__ fc_w, const float* __restrict__ fc_b,
                              const float* __restrict__ gate_w, const float* __restrict__ gate_b,
                              const float* __restrict__ hx, float* __restrict__ out_hx)
{
    __shared__ __align__(16) float As[32*68];
    __shared__ __align__(16) float Ws[32*68];
    int tid = threadIdx.x;            // 240
    int tx = tid % 15, ty = tid / 15;
    int n0 = blockIdx.x * 60;         // 0 or 60 (interleaved: even=fc, odd=gate)
    int m0 = blockIdx.y * 64;         // rows of B*6

    float acc[16];
#pragma unroll
    for (int i = 0; i < 16; i++) acc[i] = 0.f;

    for (int k0 = 0; k0 < 128; k0 += 32) {
        for (int e = tid; e < 64*32; e += 240) {
            int m = e >> 5, d = e & 31;
            As[d*68 + m] = g_raw[(size_t)(m0+m)*128 + k0 + d];
        }
        for (int e = tid; e < 32*60; e += 240) {
            int n = e >> 5, d = e & 31;
            int ngl = n0 + n; int r = ngl >> 1;
            const float* Wp = (ngl & 1) ? gate_w : fc_w;
            Ws[d*68 + n] = Wp[(size_t)r*128 + k0 + d];
        }
        __syncthreads();
#pragma unroll
        for (int kk = 0; kk < 32; kk++)
            FMA16(acc, &As[kk*68 + ty*4], &Ws[kk*68 + tx*4]);
        __syncthreads();
    }
#pragma unroll
    for (int i = 0; i < 4; i++) {
        int m = m0 + ty*4 + i;
        int b = m / 6, kb = m % 6;
        float mask = g_mask[m];
#pragma unroll
        for (int jj = 0; jj < 2; jj++) {
            int c = tx*4 + jj*2;
            int r = (n0 + c) >> 1;
            float fc = acc[i*4 + jj*2]     + fc_b[r];
            float gt = acc[i*4 + jj*2 + 1] + gate_b[r];
            float att = sigf(gt) * tanhf(fc);
            size_t oi = (size_t)b*360 + kb*60 + r;
            float hn = g_hxn[oi];
            float ho = hx[oi];
            out_hx[oi] = mask*(hn + att) + (1.f - mask)*ho;
        }
    }
}

// ---------------- launch ----------------
extern "C" void kernel_launch(void* const* d_in, const int* in_sizes, int n_in,
                              void* d_out, int out_size)
{
    const float* inp    = (const float*)d_in[0];
    const float* hx     = (const float*)d_in[1];   // [1,B,360], idx_layer=0
    const float* cx     = (const float*)d_in[2];
    const float* Wq_inp = (const float*)d_in[3];
    const float* Wk_inp = (const float*)d_in[4];
    const float* Wv_inp = (const float*)d_in[5];
    const float* Wq_c   = (const float*)d_in[6];
    const float* Wk_c   = (const float*)d_in[7];
    const float* Wv_c   = (const float*)d_in[8];
    const float* fc_w   = (const float*)d_in[9];
    const float* fc_b   = (const float*)d_in[10];
    const float* gate_w = (const float*)d_in[11];
    const float* gate_b = (const float*)d_in[12];
    const float* W_ih   = (const float*)d_in[13];
    const float* W_hh   = (const float*)d_in[14];
    const float* b_ih   = (const float*)d_in[15];
    const float* b_hh   = (const float*)d_in[16];

    float* out_hx = (float*)d_out;
    float* out_cx = (float*)d_out + (size_t)BATCH*360;

    k1_kvproj<<<dim3(8, 256), 256>>>(inp, Wk_inp + 768*256, Wv_inp + 768*240);
    k2_qproj<<<dim3(256, 6, 4), 256>>>(hx, Wq_inp);
    k3_attmask<<<2048, 256>>>();
    k4_gates<<<dim3(4, 256, 6), 240>>>(hx, W_ih, W_hh, b_ih, b_hh);
    k5_lstm<<<(BATCH*360)/256, 256>>>(cx, out_cx);
    k6_commqkv<<<dim3(256, 6, 6), 256>>>(Wq_c, Wk_c, Wv_c);
    k7_commattn<<<BATCH/4, 128>>>();
    k8_fcgate_out<<<dim3(2, 1536), 240>>>(fc_w, fc_b, gate_w, gate_b, hx, out_hx);
}

// round 4
// speedup vs baseline: 1.0514x; 1.0514x over previous
#include <cuda_runtime.h>
#include <math.h>

#define BATCH 16384
#define NINP  768
#define NHID  360
#define NBLK  6
#define BSZ   60

// ---------------- scratch ----------------
__device__ float g_kv[BATCH*496];      // [b][0:256]=Kproj (4 heads x64), [256:496]=Vproj (4 heads x60)
__device__ float g_alpha[BATCH*24];    // [b][k*4+h] = sigma(score)
__device__ float g_mask[BATCH*6];      // 0/1
__device__ float g_hxn[BATCH*360];     // LSTM hx_new (pre comm-attn)
__device__ float g_qkvc[BATCH*2304];   // [b][k*384 + {0:q,128:k,256:v}]
__device__ float g_raw[BATCH*768];     // [b][i*128 + h*32 + c]

__device__ __forceinline__ float sigf(float x){ return 1.f/(1.f+expf(-x)); }

#define LOAD_FRAG(f, p) do { \
    *(float4*)&f[0] = *(const float4*)(p); \
    *(float4*)&f[4] = *(const float4*)((p)+4); } while(0)

#define FMA8x8(acc, af, bf) do { \
  _Pragma("unroll") for (int i_ = 0; i_ < 8; i_++) \
    _Pragma("unroll") for (int j_ = 0; j_ < 8; j_++) \
      acc[i_*8+j_] = fmaf(af[i_], bf[j_], acc[i_*8+j_]); } while(0)

// ---------------- K1: KV projection  [B,768] @ [768,496] ----------------
// 128x128 tile, 256 thr, 8x8 micro
__global__ void k1_kvproj(const float* __restrict__ inp,
                          const float* __restrict__ Wk1,
                          const float* __restrict__ Wv1)
{
    __shared__ __align__(16) float As[16*132];
    __shared__ __align__(16) float Bs[16*132];
    int tid = threadIdx.x;
    int tx = tid & 15, ty = tid >> 4;
    int m0 = blockIdx.y * 128;
    int n0 = blockIdx.x * 128;
    float acc[64];
#pragma unroll
    for (int i = 0; i < 64; i++) acc[i] = 0.f;

    for (int k0 = 0; k0 < 768; k0 += 16) {
        for (int e = tid; e < 128*16; e += 256) {
            int m = e >> 4, d = e & 15;
            As[d*132 + m] = inp[(size_t)(m0+m)*768 + k0 + d];
        }
        for (int e = tid; e < 16*128; e += 256) {
            int d = e >> 7, n = e & 127;
            int ng = n0 + n;
            float v = 0.f;
            if (ng < 256)       v = Wk1[(size_t)(k0+d)*256 + ng];
            else if (ng < 496)  v = Wv1[(size_t)(k0+d)*240 + (ng-256)];
            Bs[d*132 + n] = v;
        }
        __syncthreads();
#pragma unroll
        for (int kk = 0; kk < 16; kk++) {
            float af[8], bf[8];
            LOAD_FRAG(af, &As[kk*132 + ty*8]);
            LOAD_FRAG(bf, &Bs[kk*132 + tx*8]);
            FMA8x8(acc, af, bf);
        }
        __syncthreads();
    }
#pragma unroll
    for (int i = 0; i < 8; i++) {
        int m = m0 + ty*8 + i;
#pragma unroll
        for (int j = 0; j < 8; j++) {
            int n = n0 + tx*8 + j;
            if (n < 496) g_kv[(size_t)m*496 + n] = acc[i*8+j];
        }
    }
}

// ---------------- K2: Q projection + fused attention score -> alpha ----------------
__global__ void k2_qalpha(const float* __restrict__ hx,
                          const float* __restrict__ Wq)
{
    __shared__ __align__(16) float Xs[20*132];
    __shared__ __align__(16) float Ws[20*68];
    int tid = threadIdx.x;           // 128
    int tx = tid & 7, ty = tid >> 3; // ty 0..15 rows, tx 0..7 cols
    int m0 = blockIdx.x * 128;
    int k  = blockIdx.y;
    int h  = blockIdx.z;

    float acc[64];
#pragma unroll
    for (int i = 0; i < 64; i++) acc[i] = 0.f;

    for (int d0 = 0; d0 < 60; d0 += 20) {
        for (int e = tid; e < 128*20; e += 128) {
            int m = e / 20, dd = e % 20;
            Xs[dd*132 + m] = hx[(size_t)(m0+m)*360 + k*60 + d0 + dd];
        }
        for (int e = tid; e < 20*64; e += 128) {
            int dd = e >> 6, n = e & 63;
            Ws[dd*68 + n] = Wq[(size_t)k*15360 + (d0+dd)*256 + h*64 + n];
        }
        __syncthreads();
#pragma unroll
        for (int kk = 0; kk < 20; kk++) {
            float af[8], bf[8];
            LOAD_FRAG(af, &Xs[kk*132 + ty*8]);
            LOAD_FRAG(bf, &Ws[kk*68 + tx*8]);
            FMA8x8(acc, af, bf);
        }
        __syncthreads();
    }
#pragma unroll
    for (int i = 0; i < 8; i++) {
        int gm = m0 + ty*8 + i;
        const float* kp = &g_kv[(size_t)gm*496 + h*64 + tx*8];
        float s = 0.f;
#pragma unroll
        for (int j = 0; j < 8; j++) s += acc[i*8+j] * kp[j];
        s += __shfl_xor_sync(0xffffffffu, s, 1);
        s += __shfl_xor_sync(0xffffffffu, s, 2);
        s += __shfl_xor_sync(0xffffffffu, s, 4);
        if (tx == 0) g_alpha[(size_t)gm*24 + k*4 + h] = sigf(0.125f*s);
    }
}

// ---------------- K3: top-2 null mask ----------------
__global__ void k3_mask()
{
    int b = blockIdx.x*256 + threadIdx.x;
    float4 a0 = *(const float4*)&g_alpha[(size_t)b*24 + 0];
    float4 a1 = *(const float4*)&g_alpha[(size_t)b*24 + 4];
    float4 a2 = *(const float4*)&g_alpha[(size_t)b*24 + 8];
    float4 a3 = *(const float4*)&g_alpha[(size_t)b*24 + 12];
    float4 a4 = *(const float4*)&g_alpha[(size_t)b*24 + 16];
    float4 a5 = *(const float4*)&g_alpha[(size_t)b*24 + 20];
    float nul[6];
    nul[0] = 1.f - 0.25f*(a0.x+a0.y+a0.z+a0.w);
    nul[1] = 1.f - 0.25f*(a1.x+a1.y+a1.z+a1.w);
    nul[2] = 1.f - 0.25f*(a2.x+a2.y+a2.z+a2.w);
    nul[3] = 1.f - 0.25f*(a3.x+a3.y+a3.z+a3.w);
    nul[4] = 1.f - 0.25f*(a4.x+a4.y+a4.z+a4.w);
    nul[5] = 1.f - 0.25f*(a5.x+a5.y+a5.z+a5.w);
    int i1 = 0; float m1 = nul[0];
#pragma unroll
    for (int k = 1; k < 6; k++) if (nul[k] > m1) { m1 = nul[k]; i1 = k; }
    int i2 = -1; float m2 = -1e30f;
#pragma unroll
    for (int k = 0; k < 6; k++) if (k != i1 && nul[k] > m2) { m2 = nul[k]; i2 = k; }
#pragma unroll
    for (int k = 0; k < 6; k++)
        g_mask[(size_t)b*6 + k] = (k == i1 || k == i2) ? 0.f : 1.f;
}

// ---------------- K4: fused gates GEMM (all 4 gates) + LSTM pointwise + cx_out ----------------
__global__ void k4_gates_lstm(const float* __restrict__ hx,
                              const float* __restrict__ cx,
                              const float* __restrict__ W_ih,
                              const float* __restrict__ W_hh,
                              const float* __restrict__ b_ih,
                              const float* __restrict__ b_hh,
                              float* __restrict__ out_cx)
{
    __shared__ __align__(16) float As[20*68];
    __shared__ __align__(16) float Bs[20*244];
    __shared__ float sbias[240];
    __shared__ float s_alpha[256];
    int tid = threadIdx.x;            // 240
    int tx = tid % 30, ty = tid / 30; // ty 0..7 rows(8 each), tx 0..29 cols(8 each)
    int m0 = blockIdx.x * 64;
    int k  = blockIdx.y;

    if (tid < 240) {
        int c = tid, r = c >> 2, g = c & 3;
        int rowW = g*360 + k*60 + r;
        sbias[c] = b_ih[rowW] + b_hh[rowW];
    }
    for (int e = tid; e < 256; e += 240)
        s_alpha[e] = g_alpha[(size_t)(m0 + (e >> 2))*24 + k*4 + (e & 3)];

    float acc[64];
#pragma unroll
    for (int i = 0; i < 64; i++) acc[i] = 0.f;

    for (int d0 = 0; d0 < 300; d0 += 20) {
        __syncthreads();
        for (int e = tid; e < 64*20; e += 240) {
            int m = e / 20, dd = e % 20;
            int d = d0 + dd;
            float v;
            if (d < 240) v = s_alpha[m*4 + d/60] * g_kv[(size_t)(m0+m)*496 + 256 + d];
            else         v = hx[(size_t)(m0+m)*360 + k*60 + (d-240)];
            As[dd*68 + m] = v;
        }
        for (int e = tid; e < 20*240; e += 240) {
            int c = e / 20, dd = e % 20;
            int d = d0 + dd;
            int r = c >> 2, g = c & 3;
            int rowW = g*360 + k*60 + r;
            float v;
            if (d < 240) v = W_ih[(size_t)rowW*1440 + k*240 + d];
            else         v = W_hh[(size_t)rowW*360 + k*60 + (d-240)];
            Bs[dd*244 + c] = v;
        }
        __syncthreads();
#pragma unroll
        for (int kk = 0; kk < 20; kk++) {
            float af[8], bf[8];
            LOAD_FRAG(af, &As[kk*68 + ty*8]);
            LOAD_FRAG(bf, &Bs[kk*244 + tx*8]);
            FMA8x8(acc, af, bf);
        }
    }
#pragma unroll
    for (int i = 0; i < 8; i++) {
        int b = m0 + ty*8 + i;
        float msk = g_mask[(size_t)b*6 + k];
#pragma unroll
        for (int r2 = 0; r2 < 2; r2++) {
            int r = tx*2 + r2;
            float gi = acc[i*8 + r2*4 + 0] + sbias[r*4 + 0];
            float gf = acc[i*8 + r2*4 + 1] + sbias[r*4 + 1];
            float gg = acc[i*8 + r2*4 + 2] + sbias[r*4 + 2];
            float go = acc[i*8 + r2*4 + 3] + sbias[r*4 + 3];
            size_t idx = (size_t)b*360 + k*60 + r;
            float c_old = cx[idx];
            float cn = sigf(gf)*c_old + sigf(gi)*tanhf(gg);
            float hn = sigf(go)*tanhf(cn);
            g_hxn[idx] = hn;
            out_cx[idx] = msk*cn + (1.f - msk)*c_old;
        }
    }
}

// ---------------- K6: comm QKV per block  [B,60] @ [60,384] ----------------
__global__ void k6_commqkv(const float* __restrict__ Wq_c,
                           const float* __restrict__ Wk_c,
                           const float* __restrict__ Wv_c)
{
    __shared__ __align__(16) float Xs[20*132];
    __shared__ __align__(16) float Ws[20*68];
    int tid = threadIdx.x;           // 128
    int tx = tid & 7, ty = tid >> 3;
    int m0 = blockIdx.x * 128;
    int k  = blockIdx.y;
    int ng0 = blockIdx.z * 64;       // 0..320
    const float* Wsel = (ng0 < 128) ? Wq_c : (ng0 < 256) ? Wk_c : Wv_c;
    int nc0 = (ng0 < 128) ? ng0 : (ng0 < 256) ? ng0-128 : ng0-256;

    float acc[64];
#pragma unroll
    for (int i = 0; i < 64; i++) acc[i] = 0.f;

    for (int d0 = 0; d0 < 60; d0 += 20) {
        for (int e = tid; e < 128*20; e += 128) {
            int m = e / 20, dd = e % 20;
            Xs[dd*132 + m] = g_hxn[(size_t)(m0+m)*360 + k*60 + d0 + dd];
        }
        for (int e = tid; e < 20*64; e += 128) {
            int dd = e >> 6, n = e & 63;
            Ws[dd*68 + n] = Wsel[(size_t)k*7680 + (d0+dd)*128 + nc0 + n];
        }
        __syncthreads();
#pragma unroll
        for (int kk = 0; kk < 20; kk++) {
            float af[8], bf[8];
            LOAD_FRAG(af, &Xs[kk*132 + ty*8]);
            LOAD_FRAG(bf, &Ws[kk*68 + tx*8]);
            FMA8x8(acc, af, bf);
        }
        __syncthreads();
    }
#pragma unroll
    for (int i = 0; i < 8; i++) {
        int m = m0 + ty*8 + i;
#pragma unroll
        for (int j = 0; j < 8; j++)
            g_qkvc[(size_t)m*2304 + k*384 + ng0 + tx*8 + j] = acc[i*8+j];
    }
}

// ---------------- K7: communication attention (6 tokens, 4 heads x 32) ----------------
__global__ void k7_commattn()
{
    __shared__ float sq[4][2304];
    __shared__ float ss[4][144];
    int w = threadIdx.x >> 5, lane = threadIdx.x & 31;
    int b = blockIdx.x * 4 + w;
    const float4* src = (const float4*)(g_qkvc + (size_t)b*2304);
    float4* dst = (float4*)&sq[w][0];
    for (int t = lane; t < 576; t += 32) dst[t] = src[t];
    __syncwarp();

    const float inv = 0.17677669529663687f;  // 1/sqrt(32)
    for (int p = lane; p < 144; p += 32) {
        int h = p / 36, rem = p % 36, i = rem / 6, j = rem % 6;
        const float* qv = &sq[w][i*384 + h*32];
        const float* kv = &sq[w][j*384 + 128 + h*32];
        float s = 0.f;
#pragma unroll
        for (int c = 0; c < 32; c++) s += qv[c]*kv[c];
        ss[w][p] = s * inv;
    }
    __syncwarp();
    if (lane < 24) {
        float* row = &ss[w][lane*6];
        float mx = row[0];
#pragma unroll
        for (int j = 1; j < 6; j++) mx = fmaxf(mx, row[j]);
        float ev[6]; float sum = 0.f;
#pragma unroll
        for (int j = 0; j < 6; j++) { ev[j] = expf(row[j]-mx); sum += ev[j]; }
        float is = 1.f/sum;
#pragma unroll
        for (int j = 0; j < 6; j++) row[j] = ev[j]*is;
    }
    __syncwarp();
    for (int o = lane; o < 768; o += 32) {
        int i = o >> 7, rem = o & 127, h = rem >> 5, c = rem & 31;
        const float* att = &ss[w][h*36 + i*6];
        float acc = 0.f;
#pragma unroll
        for (int j = 0; j < 6; j++) acc += att[j]*sq[w][j*384 + 256 + h*32 + c];
        g_raw[(size_t)b*768 + o] = acc;
    }
}

// ---------------- K8: fc/gate GEMM (interleaved cols) + final hx_out ----------------
__global__ void k8_fcgate_out(const float* __restrict__ fc_w, const float* __restrict__ fc_b,
                              const float* __restrict__ gate_w, const float* __restrict__ gate_b,
                              const float* __restrict__ hx, float* __restrict__ out_hx)
{
    __shared__ __align__(16) float Xs[32*132];
    __shared__ __align__(16) float Ws[32*124];
    int tid = threadIdx.x;            // 240
    int tx = tid % 15, ty = tid / 15; // ty 0..15 rows, tx 0..14 cols
    int m0 = blockIdx.x * 128;

    float acc[64];
#pragma unroll
    for (int i = 0; i < 64; i++) acc[i] = 0.f;

    for (int k0 = 0; k0 < 128; k0 += 32) {
        for (int e = tid; e < 128*32; e += 240) {
            int m = e >> 5, dd = e & 31;
            Xs[dd*132 + m] = g_raw[(size_t)(m0+m)*128 + k0 + dd];
        }
        for (int e = tid; e < 32*120; e += 240) {
            int c = e / 32, dd = e % 32;
            int r = c >> 1;
            const float* Wp = (c & 1) ? gate_w : fc_w;
            Ws[dd*124 + c] = Wp[(size_t)r*128 + k0 + dd];
        }
        __syncthreads();
#pragma unroll
        for (int kk = 0; kk < 32; kk++) {
            float af[8], bf[8];
            LOAD_FRAG(af, &Xs[kk*132 + ty*8]);
            LOAD_FRAG(bf, &Ws[kk*124 + tx*8]);
            FMA8x8(acc, af, bf);
        }
        __syncthreads();
    }
#pragma unroll
    for (int i = 0; i < 8; i++) {
        int m = m0 + ty*8 + i;
        int b = m / 6, kb = m % 6;
        float msk = g_mask[m];
#pragma unroll
        for (int jr = 0; jr < 4; jr++) {
            int r = tx*4 + jr;
            float fc = acc[i*8 + jr*2]     + fc_b[r];
            float gt = acc[i*8 + jr*2 + 1] + gate_b[r];
            float att = sigf(gt) * tanhf(fc);
            size_t idx = (size_t)b*360 + kb*60 + r;
            float hn = g_hxn[idx];
            float ho = hx[idx];
            out_hx[idx] = msk*(hn + att) + (1.f - msk)*ho;
        }
    }
}

// ---------------- launch ----------------
extern "C" void kernel_launch(void* const* d_in, const int* in_sizes, int n_in,
                              void* d_out, int out_size)
{
    const float* inp    = (const float*)d_in[0];
    const float* hx     = (const float*)d_in[1];
    const float* cx     = (const float*)d_in[2];
    const float* Wq_inp = (const float*)d_in[3];
    const float* Wk_inp = (const float*)d_in[4];
    const float* Wv_inp = (const float*)d_in[5];
    const float* Wq_c   = (const float*)d_in[6];
    const float* Wk_c   = (const float*)d_in[7];
    const float* Wv_c   = (const float*)d_in[8];
    const float* fc_w   = (const float*)d_in[9];
    const float* fc_b   = (const float*)d_in[10];
    const float* gate_w = (const float*)d_in[11];
    const float* gate_b = (const float*)d_in[12];
    const float* W_ih   = (const float*)d_in[13];
    const float* W_hh   = (const float*)d_in[14];
    const float* b_ih   = (const float*)d_in[15];
    const float* b_hh   = (const float*)d_in[16];

    float* out_hx = (float*)d_out;
    float* out_cx = (float*)d_out + (size_t)BATCH*360;

    k1_kvproj<<<dim3(4, 128), 256>>>(inp, Wk_inp + 768*256, Wv_inp + 768*240);
    k2_qalpha<<<dim3(128, 6, 4), 128>>>(hx, Wq_inp);
    k3_mask<<<64, 256>>>();
    k4_gates_lstm<<<dim3(256, 6), 240>>>(hx, cx, W_ih, W_hh, b_ih, b_hh, out_cx);
    k6_commqkv<<<dim3(128, 6, 6), 128>>>(Wq_c, Wk_c, Wv_c);
    k7_commattn<<<BATCH/4, 128>>>();
    k8_fcgate_out<<<768, 240>>>(fc_w, fc_b, gate_w, gate_b, hx, out_hx);
}

// round 5
// speedup vs baseline: 1.0811x; 1.0282x over previous
#include <cuda_runtime.h>
#include <math.h>

#define BATCH 16384
#define NINP  768
#define NHID  360
#define NBLK  6
#define BSZ   60

// ---------------- scratch ----------------
__device__ float g_kv[BATCH*496];      // [b][0:256]=Kproj (4 heads x64), [256:496]=Vproj (4 heads x60)
__device__ float g_alpha[BATCH*24];    // [b][k*4+h] = sigma(score)
__device__ float g_mask[BATCH*6];      // 0/1
__device__ float g_hxn[BATCH*360];     // LSTM hx_new (pre comm-attn)
__device__ float g_qkvc[BATCH*2304];   // [b][k*384 + {0:q,128:k,256:v}]
__device__ float g_raw[BATCH*768];     // [b][i*128 + h*32 + c]

__device__ __forceinline__ float sigf(float x){ return 1.f/(1.f+expf(-x)); }

#define LOAD_FRAG(f, p) do { \
    *(float4*)&f[0] = *(const float4*)(p); \
    *(float4*)&f[4] = *(const float4*)((p)+4); } while(0)

#define FMA8x8(acc, af, bf) do { \
  _Pragma("unroll") for (int i_ = 0; i_ < 8; i_++) \
    _Pragma("unroll") for (int j_ = 0; j_ < 8; j_++) \
      acc[i_*8+j_] = fmaf(af[i_], bf[j_], acc[i_*8+j_]); } while(0)

// ---------------- K1: KV projection  [B,768] @ [768,496] ----------------
// 128x128 tile, 256 thr, 8x8 micro, K-chunk 32
__global__ __launch_bounds__(256, 1) void k1_kvproj(const float* __restrict__ inp,
                          const float* __restrict__ Wk1,
                          const float* __restrict__ Wv1)
{
    __shared__ __align__(16) float As[32*132];
    __shared__ __align__(16) float Bs[32*132];
    int tid = threadIdx.x;
    int tx = tid & 15, ty = tid >> 4;
    int m0 = blockIdx.y * 128;
    int n0 = blockIdx.x * 128;
    float acc[64];
#pragma unroll
    for (int i = 0; i < 64; i++) acc[i] = 0.f;

    for (int k0 = 0; k0 < 768; k0 += 32) {
        for (int e = tid; e < 128*32; e += 256) {
            int m = e >> 5, d = e & 31;
            As[d*132 + m] = inp[(size_t)(m0+m)*768 + k0 + d];
        }
        for (int e = tid; e < 32*128; e += 256) {
            int d = e >> 7, n = e & 127;
            int ng = n0 + n;
            float v = 0.f;
            if (ng < 256)       v = Wk1[(size_t)(k0+d)*256 + ng];
            else if (ng < 496)  v = Wv1[(size_t)(k0+d)*240 + (ng-256)];
            Bs[d*132 + n] = v;
        }
        __syncthreads();
#pragma unroll
        for (int kk = 0; kk < 32; kk++) {
            float af[8], bf[8];
            LOAD_FRAG(af, &As[kk*132 + ty*8]);
            LOAD_FRAG(bf, &Bs[kk*132 + tx*8]);
            FMA8x8(acc, af, bf);
        }
        __syncthreads();
    }
#pragma unroll
    for (int i = 0; i < 8; i++) {
        int m = m0 + ty*8 + i;
#pragma unroll
        for (int j = 0; j < 8; j++) {
            int n = n0 + tx*8 + j;
            if (n < 496) g_kv[(size_t)m*496 + n] = acc[i*8+j];
        }
    }
}

// ---------------- K2: Q projection (all 4 heads) + fused score -> alpha ----------------
// tile 64 rows x 256 cols, 256 thr, 8x8 micro
__global__ __launch_bounds__(256, 1) void k2_qalpha(const float* __restrict__ hx,
                          const float* __restrict__ Wq)
{
    __shared__ __align__(16) float Xs[20*68];
    __shared__ __align__(16) float Ws[20*260];
    int tid = threadIdx.x;            // 256
    int tx = tid & 31, ty = tid >> 5; // ty 0..7 (rows), tx 0..31 (cols)
    int m0 = blockIdx.x * 64;
    int k  = blockIdx.y;

    float acc[64];
#pragma unroll
    for (int i = 0; i < 64; i++) acc[i] = 0.f;

    for (int d0 = 0; d0 < 60; d0 += 20) {
        for (int e = tid; e < 64*20; e += 256) {
            int m = e / 20, dd = e % 20;
            Xs[dd*68 + m] = hx[(size_t)(m0+m)*360 + k*60 + d0 + dd];
        }
        for (int e = tid; e < 20*256; e += 256) {
            int dd = e >> 8, n = e & 255;
            Ws[dd*260 + n] = Wq[(size_t)k*15360 + (d0+dd)*256 + n];
        }
        __syncthreads();
#pragma unroll
        for (int kk = 0; kk < 20; kk++) {
            float af[8], bf[8];
            LOAD_FRAG(af, &Xs[kk*68 + ty*8]);
            LOAD_FRAG(bf, &Ws[kk*260 + tx*8]);
            FMA8x8(acc, af, bf);
        }
        __syncthreads();
    }
    // fused score: q.k per head, reduce over 8-lane groups (one head each)
    int h = tx >> 3, lane8 = tx & 7;
#pragma unroll
    for (int i = 0; i < 8; i++) {
        int gm = m0 + ty*8 + i;
        const float* kp = &g_kv[(size_t)gm*496 + h*64 + lane8*8];
        float s = 0.f;
#pragma unroll
        for (int j = 0; j < 8; j++) s += acc[i*8+j] * kp[j];
        s += __shfl_xor_sync(0xffffffffu, s, 1);
        s += __shfl_xor_sync(0xffffffffu, s, 2);
        s += __shfl_xor_sync(0xffffffffu, s, 4);
        if (lane8 == 0) g_alpha[(size_t)gm*24 + k*4 + h] = sigf(0.125f*s);
    }
}

// ---------------- K3: top-2 null mask ----------------
__global__ void k3_mask()
{
    int b = blockIdx.x*256 + threadIdx.x;
    float4 a0 = *(const float4*)&g_alpha[(size_t)b*24 + 0];
    float4 a1 = *(const float4*)&g_alpha[(size_t)b*24 + 4];
    float4 a2 = *(const float4*)&g_alpha[(size_t)b*24 + 8];
    float4 a3 = *(const float4*)&g_alpha[(size_t)b*24 + 12];
    float4 a4 = *(const float4*)&g_alpha[(size_t)b*24 + 16];
    float4 a5 = *(const float4*)&g_alpha[(size_t)b*24 + 20];
    float nul[6];
    nul[0] = 1.f - 0.25f*(a0.x+a0.y+a0.z+a0.w);
    nul[1] = 1.f - 0.25f*(a1.x+a1.y+a1.z+a1.w);
    nul[2] = 1.f - 0.25f*(a2.x+a2.y+a2.z+a2.w);
    nul[3] = 1.f - 0.25f*(a3.x+a3.y+a3.z+a3.w);
    nul[4] = 1.f - 0.25f*(a4.x+a4.y+a4.z+a4.w);
    nul[5] = 1.f - 0.25f*(a5.x+a5.y+a5.z+a5.w);
    int i1 = 0; float m1 = nul[0];
#pragma unroll
    for (int k = 1; k < 6; k++) if (nul[k] > m1) { m1 = nul[k]; i1 = k; }
    int i2 = -1; float m2 = -1e30f;
#pragma unroll
    for (int k = 0; k < 6; k++) if (k != i1 && nul[k] > m2) { m2 = nul[k]; i2 = k; }
#pragma unroll
    for (int k = 0; k < 6; k++)
        g_mask[(size_t)b*6 + k] = (k == i1 || k == i2) ? 0.f : 1.f;
}

// ---------------- K4: fused gates GEMM (all 4 gates) + LSTM pointwise + cx_out ----------------
// tile 128 rows x 240 cols (gate-interleaved), 480 thr, 8x8 micro
__global__ __launch_bounds__(480, 1) void k4_gates_lstm(const float* __restrict__ hx,
                              const float* __restrict__ cx,
                              const float* __restrict__ W_ih,
                              const float* __restrict__ W_hh,
                              const float* __restrict__ b_ih,
                              const float* __restrict__ b_hh,
                              float* __restrict__ out_cx)
{
    __shared__ __align__(16) float As[20*132];
    __shared__ __align__(16) float Bs[20*244];
    __shared__ float sbias[240];
    __shared__ float s_alpha[512];
    int tid = threadIdx.x;            // 480
    int tx = tid % 30, ty = tid / 30; // ty 0..15 rows(8 each), tx 0..29 cols(8 each)
    int m0 = blockIdx.x * 128;
    int k  = blockIdx.y;

    if (tid < 240) {
        int c = tid, r = c >> 2, g = c & 3;
        int rowW = g*360 + k*60 + r;
        sbias[c] = b_ih[rowW] + b_hh[rowW];
    }
    for (int e = tid; e < 512; e += 480)
        s_alpha[e] = g_alpha[(size_t)(m0 + (e >> 2))*24 + k*4 + (e & 3)];

    float acc[64];
#pragma unroll
    for (int i = 0; i < 64; i++) acc[i] = 0.f;

    for (int d0 = 0; d0 < 300; d0 += 20) {
        __syncthreads();
        for (int e = tid; e < 128*20; e += 480) {
            int m = e / 20, dd = e % 20;
            int d = d0 + dd;
            float v;
            if (d < 240) v = s_alpha[m*4 + d/60] * g_kv[(size_t)(m0+m)*496 + 256 + d];
            else         v = hx[(size_t)(m0+m)*360 + k*60 + (d-240)];
            As[dd*132 + m] = v;
        }
        for (int e = tid; e < 20*240; e += 480) {
            int c = e / 20, dd = e % 20;
            int d = d0 + dd;
            int r = c >> 2, g = c & 3;
            int rowW = g*360 + k*60 + r;
            float v;
            if (d < 240) v = W_ih[(size_t)rowW*1440 + k*240 + d];
            else         v = W_hh[(size_t)rowW*360 + k*60 + (d-240)];
            Bs[dd*244 + c] = v;
        }
        __syncthreads();
#pragma unroll
        for (int kk = 0; kk < 20; kk++) {
            float af[8], bf[8];
            LOAD_FRAG(af, &As[kk*132 + ty*8]);
            LOAD_FRAG(bf, &Bs[kk*244 + tx*8]);
            FMA8x8(acc, af, bf);
        }
    }
#pragma unroll
    for (int i = 0; i < 8; i++) {
        int b = m0 + ty*8 + i;
        float msk = g_mask[(size_t)b*6 + k];
#pragma unroll
        for (int r2 = 0; r2 < 2; r2++) {
            int r = tx*2 + r2;
            float gi = acc[i*8 + r2*4 + 0] + sbias[r*4 + 0];
            float gf = acc[i*8 + r2*4 + 1] + sbias[r*4 + 1];
            float gg = acc[i*8 + r2*4 + 2] + sbias[r*4 + 2];
            float go = acc[i*8 + r2*4 + 3] + sbias[r*4 + 3];
            size_t idx = (size_t)b*360 + k*60 + r;
            float c_old = cx[idx];
            float cn = sigf(gf)*c_old + sigf(gi)*tanhf(gg);
            float hn = sigf(go)*tanhf(cn);
            g_hxn[idx] = hn;
            out_cx[idx] = msk*cn + (1.f - msk)*c_old;
        }
    }
}

// ---------------- K6: comm QKV per block  [B,60] @ [60,384], 128x128 tiles ----------------
__global__ __launch_bounds__(256, 1) void k6_commqkv(const float* __restrict__ Wq_c,
                           const float* __restrict__ Wk_c,
                           const float* __restrict__ Wv_c)
{
    __shared__ __align__(16) float Xs[20*132];
    __shared__ __align__(16) float Ws[20*132];
    int tid = threadIdx.x;           // 256
    int tx = tid & 15, ty = tid >> 4;
    int m0 = blockIdx.x * 128;
    int k  = blockIdx.y;
    int bz = blockIdx.z;             // 0..2
    const float* Wsel = (bz == 0) ? Wq_c : (bz == 1) ? Wk_c : Wv_c;
    int ng0 = bz * 128;

    float acc[64];
#pragma unroll
    for (int i = 0; i < 64; i++) acc[i] = 0.f;

    for (int d0 = 0; d0 < 60; d0 += 20) {
        for (int e = tid; e < 128*20; e += 256) {
            int m = e / 20, dd = e % 20;
            Xs[dd*132 + m] = g_hxn[(size_t)(m0+m)*360 + k*60 + d0 + dd];
        }
        for (int e = tid; e < 20*128; e += 256) {
            int dd = e >> 7, n = e & 127;
            Ws[dd*132 + n] = Wsel[(size_t)k*7680 + (d0+dd)*128 + n];
        }
        __syncthreads();
#pragma unroll
        for (int kk = 0; kk < 20; kk++) {
            float af[8], bf[8];
            LOAD_FRAG(af, &Xs[kk*132 + ty*8]);
            LOAD_FRAG(bf, &Ws[kk*132 + tx*8]);
            FMA8x8(acc, af, bf);
        }
        __syncthreads();
    }
#pragma unroll
    for (int i = 0; i < 8; i++) {
        int m = m0 + ty*8 + i;
#pragma unroll
        for (int j = 0; j < 8; j++)
            g_qkvc[(size_t)m*2304 + k*384 + ng0 + tx*8 + j] = acc[i*8+j];
    }
}

// ---------------- K7: communication attention (6 tokens, 4 heads x 32) ----------------
__global__ void k7_commattn()
{
    __shared__ float sq[4][2304];
    __shared__ float ss[4][144];
    int w = threadIdx.x >> 5, lane = threadIdx.x & 31;
    int b = blockIdx.x * 4 + w;
    const float4* src = (const float4*)(g_qkvc + (size_t)b*2304);
    float4* dst = (float4*)&sq[w][0];
    for (int t = lane; t < 576; t += 32) dst[t] = src[t];
    __syncwarp();

    const float inv = 0.17677669529663687f;  // 1/sqrt(32)
    for (int p = lane; p < 144; p += 32) {
        int h = p / 36, rem = p % 36, i = rem / 6, j = rem % 6;
        const float* qv = &sq[w][i*384 + h*32];
        const float* kv = &sq[w][j*384 + 128 + h*32];
        float s = 0.f;
#pragma unroll
        for (int c = 0; c < 32; c++) s += qv[c]*kv[c];
        ss[w][p] = s * inv;
    }
    __syncwarp();
    if (lane < 24) {
        float* row = &ss[w][lane*6];
        float mx = row[0];
#pragma unroll
        for (int j = 1; j < 6; j++) mx = fmaxf(mx, row[j]);
        float ev[6]; float sum = 0.f;
#pragma unroll
        for (int j = 0; j < 6; j++) { ev[j] = expf(row[j]-mx); sum += ev[j]; }
        float is = 1.f/sum;
#pragma unroll
        for (int j = 0; j < 6; j++) row[j] = ev[j]*is;
    }
    __syncwarp();
    for (int o = lane; o < 768; o += 32) {
        int i = o >> 7, rem = o & 127, h = rem >> 5, c = rem & 31;
        const float* att = &ss[w][h*36 + i*6];
        float acc = 0.f;
#pragma unroll
        for (int j = 0; j < 6; j++) acc += att[j]*sq[w][j*384 + 256 + h*32 + c];
        g_raw[(size_t)b*768 + o] = acc;
    }
}

// ---------------- K8: fc/gate GEMM (interleaved cols) + final hx_out ----------------
__global__ __launch_bounds__(240, 1) void k8_fcgate_out(const float* __restrict__ fc_w, const float* __restrict__ fc_b,
                              const float* __restrict__ gate_w, const float* __restrict__ gate_b,
                              const float* __restrict__ hx, float* __restrict__ out_hx)
{
    __shared__ __align__(16) float Xs[32*132];
    __shared__ __align__(16) float Ws[32*124];
    int tid = threadIdx.x;            // 240
    int tx = tid % 15, ty = tid / 15; // ty 0..15 rows, tx 0..14 cols
    int m0 = blockIdx.x * 128;

    float acc[64];
#pragma unroll
    for (int i = 0; i < 64; i++) acc[i] = 0.f;

    for (int k0 = 0; k0 < 128; k0 += 32) {
        for (int e = tid; e < 128*32; e += 240) {
            int m = e >> 5, dd = e & 31;
            Xs[dd*132 + m] = g_raw[(size_t)(m0+m)*128 + k0 + dd];
        }
        for (int e = tid; e < 32*120; e += 240) {
            int c = e / 32, dd = e % 32;
            int r = c >> 1;
            const float* Wp = (c & 1) ? gate_w : fc_w;
            Ws[dd*124 + c] = Wp[(size_t)r*128 + k0 + dd];
        }
        __syncthreads();
#pragma unroll
        for (int kk = 0; kk < 32; kk++) {
            float af[8], bf[8];
            LOAD_FRAG(af, &Xs[kk*132 + ty*8]);
            LOAD_FRAG(bf, &Ws[kk*124 + tx*8]);
            FMA8x8(acc, af, bf);
        }
        __syncthreads();
    }
#pragma unroll
    for (int i = 0; i < 8; i++) {
        int m = m0 + ty*8 + i;
        int b = m / 6, kb = m % 6;
        float msk = g_mask[m];
#pragma unroll
        for (int jr = 0; jr < 4; jr++) {
            int r = tx*4 + jr;
            float fc = acc[i*8 + jr*2]     + fc_b[r];
            float gt = acc[i*8 + jr*2 + 1] + gate_b[r];
            float att = sigf(gt) * tanhf(fc);
            size_t idx = (size_t)b*360 + kb*60 + r;
            float hn = g_hxn[idx];
            float ho = hx[idx];
            out_hx[idx] = msk*(hn + att) + (1.f - msk)*ho;
        }
    }
}

// ---------------- launch ----------------
extern "C" void kernel_launch(void* const* d_in, const int* in_sizes, int n_in,
                              void* d_out, int out_size)
{
    const float* inp    = (const float*)d_in[0];
    const float* hx     = (const float*)d_in[1];
    const float* cx     = (const float*)d_in[2];
    const float* Wq_inp = (const float*)d_in[3];
    const float* Wk_inp = (const float*)d_in[4];
    const float* Wv_inp = (const float*)d_in[5];
    const float* Wq_c   = (const float*)d_in[6];
    const float* Wk_c   = (const float*)d_in[7];
    const float* Wv_c   = (const float*)d_in[8];
    const float* fc_w   = (const float*)d_in[9];
    const float* fc_b   = (const float*)d_in[10];
    const float* gate_w = (const float*)d_in[11];
    const float* gate_b = (const float*)d_in[12];
    const float* W_ih   = (const float*)d_in[13];
    const float* W_hh   = (const float*)d_in[14];
    const float* b_ih   = (const float*)d_in[15];
    const float* b_hh   = (const float*)d_in[16];

    float* out_hx = (float*)d_out;
    float* out_cx = (float*)d_out + (size_t)BATCH*360;

    k1_kvproj<<<dim3(4, 128), 256>>>(inp, Wk_inp + 768*256, Wv_inp + 768*240);
    k2_qalpha<<<dim3(256, 6), 256>>>(hx, Wq_inp);
    k3_mask<<<64, 256>>>();
    k4_gates_lstm<<<dim3(128, 6), 480>>>(hx, cx, W_ih, W_hh, b_ih, b_hh, out_cx);
    k6_commqkv<<<dim3(128, 6, 3), 256>>>(Wq_c, Wk_c, Wv_c);
    k7_commattn<<<BATCH/4, 128>>>();
    k8_fcgate_out<<<768, 240>>>(fc_w, fc_b, gate_w, gate_b, hx, out_hx);
}